// round 6
// baseline (speedup 1.0000x reference)
#include <cuda_runtime.h>
#include <cstdint>

// Problem constants
#define Hdim   64
#define Wdim   64
#define HW     4096          // 64*64
#define CIN    256
#define COUT   256
#define BATCH  4
#define KK     9             // 3x3 taps
#define PDIM   (CIN * KK)    // 2304, GEMM K dimension
#define NSPLIT 8             // channel splits for offsets conv

// Scratch (static device globals; no allocation anywhere)
__device__ float g_offp[NSPLIT][BATCH * 18 * HW];        // partial offsets (per channel split)
__device__ float g_val[(size_t)BATCH * PDIM * HW];       // bilinear-sampled matrix (tf32-rounded)
__device__ float g_wdef[COUT * PDIM];                    // tf32-rounded w_def

__device__ __forceinline__ float f2tf32(float f) {
    unsigned r;
    asm("cvt.rna.tf32.f32 %0, %1;" : "=r"(r) : "f"(f));
    return __uint_as_float(r);
}

// ---------------------------------------------------------------------------
// Kernel 0: pre-round w_def to tf32 (removes cvt from GEMM mainloop)
// ---------------------------------------------------------------------------
__global__ __launch_bounds__(256) void round_a_kernel(const float* __restrict__ w)
{
    int i = blockIdx.x * blockDim.x + threadIdx.x;
    if (i < COUT * PDIM) g_wdef[i] = f2tf32(w[i]);
}

// ---------------------------------------------------------------------------
// Kernel 1: partial offsets conv. Block = 2 image rows x one 32-ch split.
// x rows staged in smem via aligned float4 loads; taps read from smem with
// halo columns. xs row stride padded to 68 floats (272B) so every
// per-(c,row) base is 16B-aligned for the float4 stores.
// ---------------------------------------------------------------------------
__global__ __launch_bounds__(128) void offsets_part_kernel(
    const float* __restrict__ x, const float* __restrict__ w_off)
{
    __shared__ float ws[8][9][20];    // [c][tap][oc] padded
    __shared__ float xs[8][4][68];    // [c][row r][col]; cols 0..63 data, 64/65 zero halos

    const int blk   = blockIdx.x;       // 0..127
    const int split = blockIdx.y;       // 0..7
    const int b     = blk >> 5;
    const int row2  = (blk & 31) * 2;
    const int hr    = threadIdx.x >> 6;   // 0/1
    const int wo    = threadIdx.x & 63;

    // halo column indices (computed once)
    const int cxm1 = (wo == 0)  ? 64 : wo - 1;
    const int cx0  = wo;
    const int cxp1 = (wo == 63) ? 65 : wo + 1;

    // zero the halo slots once
    if (threadIdx.x < 64) {
        int c = threadIdx.x >> 3;
        int r = (threadIdx.x >> 1) & 3;
        xs[c][r][64 + (threadIdx.x & 1)] = 0.f;
    }

    float acc[18];
#pragma unroll
    for (int o = 0; o < 18; o++) acc[o] = 0.f;

    const float* xb = x + (size_t)b * CIN * HW;
    const int cbase = split * (CIN / NSPLIT);

    // x staging map: thread -> (channel, row, 16-float segment)
    const int lc  = threadIdx.x >> 4;        // 0..7
    const int lr  = (threadIdx.x >> 2) & 3;  // 0..3
    const int lsg = (threadIdx.x & 3) * 16;  // 0,16,32,48
    const int ly  = row2 - 1 + lr;
    const bool lyv = (ly >= 0) && (ly < Hdim);

    for (int c0 = cbase; c0 < cbase + CIN / NSPLIT; c0 += 8) {
        __syncthreads();
        // stage weights [c][tap][oc]
        for (int i = threadIdx.x; i < 18 * 8 * 9; i += 128) {
            int oc = i / 72; int rem = i % 72; int c = rem / 9; int tap = rem % 9;
            ws[c][tap][oc] = w_off[(size_t)oc * CIN * 9 + (size_t)(c0 + c) * 9 + tap];
        }
        // stage x rows: 16 floats per thread, aligned float4
        {
            float4 v[4];
            if (lyv) {
                const float* xr = xb + (size_t)(c0 + lc) * HW + ly * Wdim + lsg;
#pragma unroll
                for (int j = 0; j < 4; j++) v[j] = *(const float4*)(xr + j * 4);
            } else {
#pragma unroll
                for (int j = 0; j < 4; j++) v[j] = make_float4(0.f, 0.f, 0.f, 0.f);
            }
#pragma unroll
            for (int j = 0; j < 4; j++)
                *(float4*)&xs[lc][lr][lsg + j * 4] = v[j];
        }
        __syncthreads();

#pragma unroll
        for (int c = 0; c < 8; c++) {
            float xv[9];
#pragma unroll
            for (int ky = 0; ky < 3; ky++) {
                const float* row = xs[c][hr + ky];
                xv[ky * 3 + 0] = row[cxm1];
                xv[ky * 3 + 1] = row[cx0];
                xv[ky * 3 + 2] = row[cxp1];
            }
#pragma unroll
            for (int tap = 0; tap < 9; tap++) {
                float xt = xv[tap];
#pragma unroll
                for (int o = 0; o < 18; o++)
                    acc[o] += xt * ws[c][tap][o];
            }
        }
    }

    const int hw = (row2 + hr) * Wdim + wo;
#pragma unroll
    for (int o = 0; o < 18; o++)
        g_offp[split][((size_t)b * 18 + o) * HW + hw] = acc[o];
}

// ---------------------------------------------------------------------------
// Kernel 2: bilinear gather -> g_val[b][c*9+k][hw] (stored tf32-rounded).
// Sums the 8 offset partials inline.
// ---------------------------------------------------------------------------
__global__ __launch_bounds__(256) void gather_kernel(const float* __restrict__ x)
{
    int idx = blockIdx.x * blockDim.x + threadIdx.x;
    if (idx >= BATCH * KK * HW) return;
    int hw = idx & 4095;
    int k  = (idx >> 12) % KK;
    int b  = idx / (KK * HW);
    int ho = hw >> 6, wo = hw & 63;
    int ky = k / 3,  kx = k % 3;

    const size_t oy = ((size_t)b * 18 + 2 * k + 0) * HW + hw;
    const size_t ox = ((size_t)b * 18 + 2 * k + 1) * HW + hw;
    float dy = 0.f, dx = 0.f;
#pragma unroll
    for (int s = 0; s < NSPLIT; s++) {
        dy += g_offp[s][oy];
        dx += g_offp[s][ox];
    }

    float py = (float)(ho - 1 + ky) + dy;
    float px = (float)(wo - 1 + kx) + dx;
    float y0f = floorf(py), x0f = floorf(px);
    int   y0 = (int)y0f,    x0 = (int)x0f;
    float wy1 = py - y0f, wx1 = px - x0f;
    float wy0 = 1.f - wy1, wx0 = 1.f - wx1;
    int y1 = y0 + 1, x1 = x0 + 1;

    bool vy0 = (y0 >= 0) & (y0 < Hdim);
    bool vy1 = (y1 >= 0) & (y1 < Hdim);
    bool vx0 = (x0 >= 0) & (x0 < Wdim);
    bool vx1 = (x1 >= 0) & (x1 < Wdim);

    float w00 = (vy0 && vx0) ? wy0 * wx0 : 0.f;
    float w01 = (vy0 && vx1) ? wy0 * wx1 : 0.f;
    float w10 = (vy1 && vx0) ? wy1 * wx0 : 0.f;
    float w11 = (vy1 && vx1) ? wy1 * wx1 : 0.f;

    int y0c = min(max(y0, 0), Hdim - 1), y1c = min(max(y1, 0), Hdim - 1);
    int x0c = min(max(x0, 0), Wdim - 1), x1c = min(max(x1, 0), Wdim - 1);
    int i00 = y0c * Wdim + x0c, i01 = y0c * Wdim + x1c;
    int i10 = y1c * Wdim + x0c, i11 = y1c * Wdim + x1c;

    const float* xb = x + (size_t)b * CIN * HW;
    float* vout = g_val + ((size_t)b * PDIM + k) * HW + hw;   // p = c*9 + k

    for (int c = 0; c < CIN; c++) {
        const float* xc = xb + c * HW;
        float v = w00 * __ldg(xc + i00) + w01 * __ldg(xc + i01)
                + w10 * __ldg(xc + i10) + w11 * __ldg(xc + i11);
        vout[(size_t)c * KK * HW] = f2tf32(v);
    }
}

// ---------------------------------------------------------------------------
// Kernel 3: TF32 tensor-core GEMM  C[b] = g_wdef[256,2304] * g_val[b][2304,4096]
// Operands pre-rounded upstream; single __syncthreads per K-tile.
// Block tile 128x128, BK=16, 256 threads (8 warps 2x4), warp = 64x32.
// Smem k dim permuted within each 8-group so fragment loads are LDS.64.
// ---------------------------------------------------------------------------
#define BM 128
#define BN 128
#define BK 16
#define KPAD 18   // padded floats per smem row (float2 accesses only)

__device__ __forceinline__ void mma_tf32(float4& d, float2 alo, float2 ahi, float2 bb) {
    asm volatile(
        "mma.sync.aligned.m16n8k8.row.col.f32.tf32.tf32.f32 "
        "{%0,%1,%2,%3}, {%4,%5,%6,%7}, {%8,%9}, {%0,%1,%2,%3};"
        : "+f"(d.x), "+f"(d.y), "+f"(d.z), "+f"(d.w)
        : "r"(__float_as_uint(alo.x)), "r"(__float_as_uint(ahi.x)),
          "r"(__float_as_uint(alo.y)), "r"(__float_as_uint(ahi.y)),
          "r"(__float_as_uint(bb.x)),  "r"(__float_as_uint(bb.y)));
}

__global__ __launch_bounds__(256) void mma_gemm_kernel(float* __restrict__ C)
{
    __shared__ float As[2][BM][KPAD];
    __shared__ float Bs[2][BN][KPAD];

    const int b  = blockIdx.z;
    const float* Bp = g_val + (size_t)b * PDIM * HW;
    float*       Cp = C     + (size_t)b * COUT * HW;
    const int m0 = blockIdx.y * BM;
    const int n0 = blockIdx.x * BN;

    const int tid  = threadIdx.x;
    const int warp = tid >> 5;
    const int lane = tid & 31;
    const int g = lane >> 2;            // 0..7
    const int t = lane & 3;             // 0..3
    const int wm = (warp >> 2) * 64;    // warp M offset: 0 or 64
    const int wn = (warp & 3) * 32;     // warp N offset: 0..96

    float4 acc[4][4];
#pragma unroll
    for (int i = 0; i < 4; i++)
#pragma unroll
        for (int j = 0; j < 4; j++) acc[i][j] = make_float4(0.f, 0.f, 0.f, 0.f);

    // gmem load mapping
    const int am = tid >> 1;                 // A row within tile, 0..127
    const int aq = (tid & 1) * 2;            // first of 2 quads (k4 index)
    const float* aptr = g_wdef + (size_t)(m0 + am) * PDIM + aq * 4;
    const int bk = tid >> 4;                 // B k-row within tile, 0..15
    const int bn = (tid & 15) * 4;           // B n offset, 0..60
    const float* bptr = Bp + (size_t)bk * HW + n0 + bn;

    // physical (permuted) k column for B row bk: pairs {t, t+4} adjacent
    const int bphys = 8 * (bk >> 3) + 2 * (bk & 3) + ((bk >> 2) & 1);

    float4 pa[2], pb[2];
    const int nk = PDIM / BK;   // 144

    // prologue: load tile 0, commit to stage 0
    pa[0] = *(const float4*)(aptr);
    pa[1] = *(const float4*)(aptr + 4);
    pb[0] = *(const float4*)(bptr);
    pb[1] = *(const float4*)(bptr + 64);
#pragma unroll
    for (int j = 0; j < 2; j++) {
        const int q = aq + j;
        const int base = 8 * (q >> 1) + (q & 1);
        float4 v = pa[j];
        As[0][am][base + 0] = v.x;
        As[0][am][base + 2] = v.y;
        As[0][am][base + 4] = v.z;
        As[0][am][base + 6] = v.w;
    }
#pragma unroll
    for (int j = 0; j < 2; j++) {
        const int n = bn + 64 * j;
        float4 v = pb[j];
        Bs[0][n + 0][bphys] = v.x;
        Bs[0][n + 1][bphys] = v.y;
        Bs[0][n + 2][bphys] = v.z;
        Bs[0][n + 3][bphys] = v.w;
    }
    __syncthreads();

    for (int it = 0; it < nk; it++) {
        const int s = it & 1;
        const bool more = (it + 1 < nk);

        // prefetch next tile from gmem (latency hidden by compute below)
        if (more) {
            const int kt = (it + 1) * BK;
            pa[0] = *(const float4*)(aptr + kt);
            pa[1] = *(const float4*)(aptr + kt + 4);
            pb[0] = *(const float4*)(bptr + (size_t)kt * HW);
            pb[1] = *(const float4*)(bptr + (size_t)kt * HW + 64);
        }

        // compute 2 k8-steps from stage s
#pragma unroll
        for (int k8 = 0; k8 < 2; k8++) {
            const int cb = k8 * 8 + 2 * t;
            float2 alo[4], ahi[4], bb[4];
#pragma unroll
            for (int mt = 0; mt < 4; mt++) {
                alo[mt] = *(const float2*)&As[s][wm + mt * 16 + g][cb];
                ahi[mt] = *(const float2*)&As[s][wm + mt * 16 + g + 8][cb];
            }
#pragma unroll
            for (int nt = 0; nt < 4; nt++)
                bb[nt] = *(const float2*)&Bs[s][wn + nt * 8 + g][cb];
#pragma unroll
            for (int mt = 0; mt < 4; mt++)
#pragma unroll
                for (int nt = 0; nt < 4; nt++)
                    mma_tf32(acc[mt][nt], alo[mt], ahi[mt], bb[nt]);
        }

        // commit prefetched tile to the other stage; one barrier per iter
        if (more) {
            const int d = s ^ 1;
#pragma unroll
            for (int j = 0; j < 2; j++) {
                const int q = aq + j;
                const int base = 8 * (q >> 1) + (q & 1);
                float4 v = pa[j];
                As[d][am][base + 0] = v.x;
                As[d][am][base + 2] = v.y;
                As[d][am][base + 4] = v.z;
                As[d][am][base + 6] = v.w;
            }
#pragma unroll
            for (int j = 0; j < 2; j++) {
                const int n = bn + 64 * j;
                float4 v = pb[j];
                Bs[d][n + 0][bphys] = v.x;
                Bs[d][n + 1][bphys] = v.y;
                Bs[d][n + 2][bphys] = v.z;
                Bs[d][n + 3][bphys] = v.w;
            }
        }
        __syncthreads();
    }

    // epilogue: D fragment -> gmem (c0,c1 at row g col 2t; c2,c3 at row g+8)
#pragma unroll
    for (int mt = 0; mt < 4; mt++) {
#pragma unroll
        for (int nt = 0; nt < 4; nt++) {
            const int row = m0 + wm + mt * 16 + g;
            const int col = n0 + wn + nt * 8 + 2 * t;
            float4 d = acc[mt][nt];
            *(float2*)(Cp + (size_t)row * HW + col)       = make_float2(d.x, d.y);
            *(float2*)(Cp + (size_t)(row + 8) * HW + col) = make_float2(d.z, d.w);
        }
    }
}

// ---------------------------------------------------------------------------
extern "C" void kernel_launch(void* const* d_in, const int* in_sizes, int n_in,
                              void* d_out, int out_size)
{
    const float* x     = (const float*)d_in[0];   // (4,256,64,64)
    const float* w_def = (const float*)d_in[1];   // (256,256,3,3)
    const float* w_off = (const float*)d_in[2];   // (18,256,3,3)
    float* out = (float*)d_out;                   // (4,256,64,64)

    round_a_kernel<<<(COUT * PDIM + 255) / 256, 256>>>(w_def);
    offsets_part_kernel<<<dim3(BATCH * 32, NSPLIT), 128>>>(x, w_off);
    gather_kernel<<<(BATCH * KK * HW + 255) / 256, 256>>>(x);
    mma_gemm_kernel<<<dim3(HW / BN, COUT / BM, BATCH), 256>>>(out);
}

// round 8
// speedup vs baseline: 1.0447x; 1.0447x over previous
#include <cuda_runtime.h>
#include <cstdint>

// Problem constants
#define Hdim   64
#define Wdim   64
#define HW     4096          // 64*64
#define CIN    256
#define COUT   256
#define BATCH  4
#define KK     9             // 3x3 taps
#define PDIM   (CIN * KK)    // 2304, GEMM K dimension
#define NSPLIT 8             // channel splits for offsets conv

// Scratch (static device globals; no allocation anywhere)
__device__ float g_offp[NSPLIT][BATCH * 18 * HW];        // partial offsets (per channel split)
__device__ float g_val[(size_t)BATCH * PDIM * HW];       // bilinear-sampled matrix (tf32-rounded)
__device__ float g_wdef[COUT * PDIM];                    // tf32-rounded w_def

__device__ __forceinline__ float f2tf32(float f) {
    unsigned r;
    asm("cvt.rna.tf32.f32 %0, %1;" : "=r"(r) : "f"(f));
    return __uint_as_float(r);
}

// ---------------------------------------------------------------------------
// Kernel 0: pre-round w_def to tf32
// ---------------------------------------------------------------------------
__global__ __launch_bounds__(256) void round_a_kernel(const float* __restrict__ w)
{
    int i = blockIdx.x * blockDim.x + threadIdx.x;
    if (i < COUT * PDIM) g_wdef[i] = f2tf32(w[i]);
}

// ---------------------------------------------------------------------------
// Kernel 1: partial offsets conv (unchanged; passing since round 6)
// ---------------------------------------------------------------------------
__global__ __launch_bounds__(128) void offsets_part_kernel(
    const float* __restrict__ x, const float* __restrict__ w_off)
{
    __shared__ float ws[8][9][20];
    __shared__ float xs[8][4][68];

    const int blk   = blockIdx.x;
    const int split = blockIdx.y;
    const int b     = blk >> 5;
    const int row2  = (blk & 31) * 2;
    const int hr    = threadIdx.x >> 6;
    const int wo    = threadIdx.x & 63;

    const int cxm1 = (wo == 0)  ? 64 : wo - 1;
    const int cx0  = wo;
    const int cxp1 = (wo == 63) ? 65 : wo + 1;

    if (threadIdx.x < 64) {
        int c = threadIdx.x >> 3;
        int r = (threadIdx.x >> 1) & 3;
        xs[c][r][64 + (threadIdx.x & 1)] = 0.f;
    }

    float acc[18];
#pragma unroll
    for (int o = 0; o < 18; o++) acc[o] = 0.f;

    const float* xb = x + (size_t)b * CIN * HW;
    const int cbase = split * (CIN / NSPLIT);

    const int lc  = threadIdx.x >> 4;
    const int lr  = (threadIdx.x >> 2) & 3;
    const int lsg = (threadIdx.x & 3) * 16;
    const int ly  = row2 - 1 + lr;
    const bool lyv = (ly >= 0) && (ly < Hdim);

    for (int c0 = cbase; c0 < cbase + CIN / NSPLIT; c0 += 8) {
        __syncthreads();
        for (int i = threadIdx.x; i < 18 * 8 * 9; i += 128) {
            int oc = i / 72; int rem = i % 72; int c = rem / 9; int tap = rem % 9;
            ws[c][tap][oc] = w_off[(size_t)oc * CIN * 9 + (size_t)(c0 + c) * 9 + tap];
        }
        {
            float4 v[4];
            if (lyv) {
                const float* xr = xb + (size_t)(c0 + lc) * HW + ly * Wdim + lsg;
#pragma unroll
                for (int j = 0; j < 4; j++) v[j] = *(const float4*)(xr + j * 4);
            } else {
#pragma unroll
                for (int j = 0; j < 4; j++) v[j] = make_float4(0.f, 0.f, 0.f, 0.f);
            }
#pragma unroll
            for (int j = 0; j < 4; j++)
                *(float4*)&xs[lc][lr][lsg + j * 4] = v[j];
        }
        __syncthreads();

#pragma unroll
        for (int c = 0; c < 8; c++) {
            float xv[9];
#pragma unroll
            for (int ky = 0; ky < 3; ky++) {
                const float* row = xs[c][hr + ky];
                xv[ky * 3 + 0] = row[cxm1];
                xv[ky * 3 + 1] = row[cx0];
                xv[ky * 3 + 2] = row[cxp1];
            }
#pragma unroll
            for (int tap = 0; tap < 9; tap++) {
                float xt = xv[tap];
#pragma unroll
                for (int o = 0; o < 18; o++)
                    acc[o] += xt * ws[c][tap][o];
            }
        }
    }

    const int hw = (row2 + hr) * Wdim + wo;
#pragma unroll
    for (int o = 0; o < 18; o++)
        g_offp[split][((size_t)b * 18 + o) * HW + hw] = acc[o];
}

// ---------------------------------------------------------------------------
// Kernel 2: bilinear gather -> g_val[b][c*9+k][hw], tf32-rounded (unchanged)
// ---------------------------------------------------------------------------
__global__ __launch_bounds__(256) void gather_kernel(const float* __restrict__ x)
{
    int idx = blockIdx.x * blockDim.x + threadIdx.x;
    if (idx >= BATCH * KK * HW) return;
    int hw = idx & 4095;
    int k  = (idx >> 12) % KK;
    int b  = idx / (KK * HW);
    int ho = hw >> 6, wo = hw & 63;
    int ky = k / 3,  kx = k % 3;

    const size_t oy = ((size_t)b * 18 + 2 * k + 0) * HW + hw;
    const size_t ox = ((size_t)b * 18 + 2 * k + 1) * HW + hw;
    float dy = 0.f, dx = 0.f;
#pragma unroll
    for (int s = 0; s < NSPLIT; s++) {
        dy += g_offp[s][oy];
        dx += g_offp[s][ox];
    }

    float py = (float)(ho - 1 + ky) + dy;
    float px = (float)(wo - 1 + kx) + dx;
    float y0f = floorf(py), x0f = floorf(px);
    int   y0 = (int)y0f,    x0 = (int)x0f;
    float wy1 = py - y0f, wx1 = px - x0f;
    float wy0 = 1.f - wy1, wx0 = 1.f - wx1;
    int y1 = y0 + 1, x1 = x0 + 1;

    bool vy0 = (y0 >= 0) & (y0 < Hdim);
    bool vy1 = (y1 >= 0) & (y1 < Hdim);
    bool vx0 = (x0 >= 0) & (x0 < Wdim);
    bool vx1 = (x1 >= 0) & (x1 < Wdim);

    float w00 = (vy0 && vx0) ? wy0 * wx0 : 0.f;
    float w01 = (vy0 && vx1) ? wy0 * wx1 : 0.f;
    float w10 = (vy1 && vx0) ? wy1 * wx0 : 0.f;
    float w11 = (vy1 && vx1) ? wy1 * wx1 : 0.f;

    int y0c = min(max(y0, 0), Hdim - 1), y1c = min(max(y1, 0), Hdim - 1);
    int x0c = min(max(x0, 0), Wdim - 1), x1c = min(max(x1, 0), Wdim - 1);
    int i00 = y0c * Wdim + x0c, i01 = y0c * Wdim + x1c;
    int i10 = y1c * Wdim + x0c, i11 = y1c * Wdim + x1c;

    const float* xb = x + (size_t)b * CIN * HW;
    float* vout = g_val + ((size_t)b * PDIM + k) * HW + hw;

    for (int c = 0; c < CIN; c++) {
        const float* xc = xb + c * HW;
        float v = w00 * __ldg(xc + i00) + w01 * __ldg(xc + i01)
                + w10 * __ldg(xc + i10) + w11 * __ldg(xc + i11);
        vout[(size_t)c * KK * HW] = f2tf32(v);
    }
}

// ---------------------------------------------------------------------------
// Kernel 3: TF32 mma.sync GEMM  C[b] = g_wdef[256,2304] * g_val[b][2304,4096]
// Block 128x128, BK=16, 256 thr (8 warps 2x4), warp 64x32.
// Smem k-dim 4-way permuted: phys(k) = 4*(k&3) + ((k>>2)&1) + 2*((k>>3)&1),
// row stride 20 floats. One LDS.128 per fragment row covers BOTH k8 steps,
// conflict-free (bank16 = (5g+t) mod 8 bijective).
// A staged as 4 STS.64 pairs (k, k+4); B: each warp owns a (k,k+4) row pair,
// lane-interleaved n (n = lane + 32j) -> coalesced LDG.32 + 4 STS.64 (2-way).
// ---------------------------------------------------------------------------
#define BM 128
#define BN 128
#define BK 16
#define SA 20   // smem row stride in floats (80B: LDS.128-aligned, frag conflict-free)

__device__ __forceinline__ void mma_tf32(float4& d, float a0, float a1, float a2, float a3,
                                         float b0, float b1) {
    asm volatile(
        "mma.sync.aligned.m16n8k8.row.col.f32.tf32.tf32.f32 "
        "{%0,%1,%2,%3}, {%4,%5,%6,%7}, {%8,%9}, {%0,%1,%2,%3};"
        : "+f"(d.x), "+f"(d.y), "+f"(d.z), "+f"(d.w)
        : "r"(__float_as_uint(a0)), "r"(__float_as_uint(a1)),
          "r"(__float_as_uint(a2)), "r"(__float_as_uint(a3)),
          "r"(__float_as_uint(b0)), "r"(__float_as_uint(b1)));
}

__global__ __launch_bounds__(256, 2) void mma_gemm_kernel(float* __restrict__ C)
{
    __shared__ float As[2][BM][SA];
    __shared__ float Bs[2][BN][SA];

    const int b  = blockIdx.z;
    const float* Bp = g_val + (size_t)b * PDIM * HW;
    float*       Cp = C     + (size_t)b * COUT * HW;
    const int m0 = blockIdx.y * BM;
    const int n0 = blockIdx.x * BN;

    const int tid  = threadIdx.x;
    const int warp = tid >> 5;
    const int lane = tid & 31;
    const int g = lane >> 2;            // 0..7
    const int t = lane & 3;             // 0..3
    const int wm = (warp >> 2) * 64;    // warp M offset
    const int wn = (warp & 3) * 32;     // warp N offset

    float4 acc[4][4];
#pragma unroll
    for (int i = 0; i < 4; i++)
#pragma unroll
        for (int j = 0; j < 4; j++) acc[i][j] = make_float4(0.f, 0.f, 0.f, 0.f);

    // A staging map: thread -> (row, k-half). Loads 2 float4 (k = 8h..8h+7).
    const int arow = tid >> 1, ah = tid & 1;
    const float* aptr = g_wdef + (size_t)(m0 + arow) * PDIM + ah * 8;

    // B staging map: warp pk owns k-rows (krl, krl+4); lanes cover n = lane+32j.
    const int pk   = warp;
    const int krl  = (pk & 3) + ((pk >> 2) << 3);
    const int bphys = ((pk & 3) << 2) + ((pk >> 2) << 1);   // phys col of pair
    const float* bptr_lo = Bp + (size_t)krl * HW + n0 + lane;
    const float* bptr_hi = bptr_lo + 4 * HW;

    float4 a0, a1;
    float bl[4], bh[4];
    const int nk = PDIM / BK;   // 144

    // prologue: load tile 0, commit to stage 0
    a0 = *(const float4*)(aptr);
    a1 = *(const float4*)(aptr + 4);
#pragma unroll
    for (int j = 0; j < 4; j++) {
        bl[j] = bptr_lo[32 * j];
        bh[j] = bptr_hi[32 * j];
    }
    {
        const float* a0p = (const float*)&a0;
        const float* a1p = (const float*)&a1;
#pragma unroll
        for (int j = 0; j < 4; j++)
            *(float2*)&As[0][arow][4 * j + 2 * ah] = make_float2(a0p[j], a1p[j]);
#pragma unroll
        for (int j = 0; j < 4; j++)
            *(float2*)&Bs[0][lane + 32 * j][bphys] = make_float2(bl[j], bh[j]);
    }
    __syncthreads();

    for (int it = 0; it < nk; it++) {
        const int s = it & 1;
        const bool more = (it + 1 < nk);

        // prefetch next tile
        if (more) {
            const size_t kt = (size_t)(it + 1) * BK;
            a0 = *(const float4*)(aptr + kt);
            a1 = *(const float4*)(aptr + kt + 4);
#pragma unroll
            for (int j = 0; j < 4; j++) {
                bl[j] = bptr_lo[kt * HW + 32 * j];
                bh[j] = bptr_hi[kt * HW + 32 * j];
            }
        }

        // compute: B fragments once, A in two mt-halves (caps live regs)
        {
            float4 BB[4];
#pragma unroll
            for (int nt = 0; nt < 4; nt++)
                BB[nt] = *(const float4*)&Bs[s][wn + nt * 8 + g][4 * t];

#pragma unroll
            for (int half = 0; half < 2; half++) {
                float4 AL[2], AH[2];
#pragma unroll
                for (int m = 0; m < 2; m++) {
                    const int mr = wm + (half * 2 + m) * 16 + g;
                    AL[m] = *(const float4*)&As[s][mr][4 * t];
                    AH[m] = *(const float4*)&As[s][mr + 8][4 * t];
                }
#pragma unroll
                for (int m = 0; m < 2; m++) {
                    const int mt = half * 2 + m;
#pragma unroll
                    for (int nt = 0; nt < 4; nt++) {
                        mma_tf32(acc[mt][nt], AL[m].x, AH[m].x, AL[m].y, AH[m].y,
                                 BB[nt].x, BB[nt].y);
                        mma_tf32(acc[mt][nt], AL[m].z, AH[m].z, AL[m].w, AH[m].w,
                                 BB[nt].z, BB[nt].w);
                    }
                }
            }
        }

        // commit prefetched tile to other stage; one barrier per iter
        if (more) {
            const int d = s ^ 1;
            const float* a0p = (const float*)&a0;
            const float* a1p = (const float*)&a1;
#pragma unroll
            for (int j = 0; j < 4; j++)
                *(float2*)&As[d][arow][4 * j + 2 * ah] = make_float2(a0p[j], a1p[j]);
#pragma unroll
            for (int j = 0; j < 4; j++)
                *(float2*)&Bs[d][lane + 32 * j][bphys] = make_float2(bl[j], bh[j]);
        }
        __syncthreads();
    }

    // epilogue: D fragments -> gmem
#pragma unroll
    for (int mt = 0; mt < 4; mt++) {
#pragma unroll
        for (int nt = 0; nt < 4; nt++) {
            const int row = m0 + wm + mt * 16 + g;
            const int col = n0 + wn + nt * 8 + 2 * t;
            float4 d = acc[mt][nt];
            *(float2*)(Cp + (size_t)row * HW + col)       = make_float2(d.x, d.y);
            *(float2*)(Cp + (size_t)(row + 8) * HW + col) = make_float2(d.z, d.w);
        }
    }
}

// ---------------------------------------------------------------------------
extern "C" void kernel_launch(void* const* d_in, const int* in_sizes, int n_in,
                              void* d_out, int out_size)
{
    const float* x     = (const float*)d_in[0];   // (4,256,64,64)
    const float* w_def = (const float*)d_in[1];   // (256,256,3,3)
    const float* w_off = (const float*)d_in[2];   // (18,256,3,3)
    float* out = (float*)d_out;                   // (4,256,64,64)

    round_a_kernel<<<(COUT * PDIM + 255) / 256, 256>>>(w_def);
    offsets_part_kernel<<<dim3(BATCH * 32, NSPLIT), 128>>>(x, w_off);
    gather_kernel<<<(BATCH * KK * HW + 255) / 256, 256>>>(x);
    mma_gemm_kernel<<<dim3(HW / BN, COUT / BM, BATCH), 256>>>(out);
}

// round 9
// speedup vs baseline: 1.1974x; 1.1461x over previous
#include <cuda_runtime.h>
#include <cstdint>

// Problem constants
#define Hdim   64
#define Wdim   64
#define HW     4096          // 64*64
#define CIN    256
#define COUT   256
#define BATCH  4
#define KK     9             // 3x3 taps
#define PDIM   (CIN * KK)    // 2304, GEMM K dimension
#define NSPLIT 8             // channel splits for offsets conv

// Scratch (static device globals; no allocation anywhere)
__device__ float g_offp[NSPLIT][BATCH * 18 * HW];        // partial offsets (per channel split)
__device__ float g_val[(size_t)BATCH * PDIM * HW];       // bilinear-sampled matrix (tf32-rounded)
__device__ float g_wdefP[COUT * PDIM];                   // tf32-rounded, k-permuted w_def

__device__ __forceinline__ float f2tf32(float f) {
    unsigned r;
    asm("cvt.rna.tf32.f32 %0, %1;" : "=r"(r) : "f"(f));
    return __uint_as_float(r);
}

__device__ __forceinline__ uint32_t smem_u32(const void* p) {
    uint32_t a;
    asm("{ .reg .u64 t; cvta.to.shared.u64 t, %1; cvt.u32.u64 %0, t; }" : "=r"(a) : "l"(p));
    return a;
}
__device__ __forceinline__ void cp16(uint32_t dst, const void* src) {
    asm volatile("cp.async.cg.shared.global [%0], [%1], 16;" :: "r"(dst), "l"(src));
}
#define CP_COMMIT() asm volatile("cp.async.commit_group;" ::: "memory")
#define CP_WAIT0()  asm volatile("cp.async.wait_group 0;" ::: "memory")

// ---------------------------------------------------------------------------
// Kernel 0: pre-round w_def to tf32 AND pre-permute k within each 16-group:
// stored float4 group p covers k = {t, t+4, t+8, t+12}. phys p -> orig k:
// k = (p>>2) + 4*(p&1) + 8*((p>>1)&1).
// ---------------------------------------------------------------------------
__global__ __launch_bounds__(256) void round_a_kernel(const float* __restrict__ w)
{
    int i = blockIdx.x * blockDim.x + threadIdx.x;
    if (i >= COUT * PDIM) return;
    int m   = i / PDIM;
    int pos = i % PDIM;
    int kt  = pos & ~15;
    int p   = pos & 15;
    int k   = (p >> 2) + 4 * (p & 1) + 8 * ((p >> 1) & 1);
    g_wdefP[i] = f2tf32(w[(size_t)m * PDIM + kt + k]);
}

// ---------------------------------------------------------------------------
// Kernel 1: partial offsets conv (unchanged; passing since round 6)
// ---------------------------------------------------------------------------
__global__ __launch_bounds__(128) void offsets_part_kernel(
    const float* __restrict__ x, const float* __restrict__ w_off)
{
    __shared__ float ws[8][9][20];
    __shared__ float xs[8][4][68];

    const int blk   = blockIdx.x;
    const int split = blockIdx.y;
    const int b     = blk >> 5;
    const int row2  = (blk & 31) * 2;
    const int hr    = threadIdx.x >> 6;
    const int wo    = threadIdx.x & 63;

    const int cxm1 = (wo == 0)  ? 64 : wo - 1;
    const int cx0  = wo;
    const int cxp1 = (wo == 63) ? 65 : wo + 1;

    if (threadIdx.x < 64) {
        int c = threadIdx.x >> 3;
        int r = (threadIdx.x >> 1) & 3;
        xs[c][r][64 + (threadIdx.x & 1)] = 0.f;
    }

    float acc[18];
#pragma unroll
    for (int o = 0; o < 18; o++) acc[o] = 0.f;

    const float* xb = x + (size_t)b * CIN * HW;
    const int cbase = split * (CIN / NSPLIT);

    const int lc  = threadIdx.x >> 4;
    const int lr  = (threadIdx.x >> 2) & 3;
    const int lsg = (threadIdx.x & 3) * 16;
    const int ly  = row2 - 1 + lr;
    const bool lyv = (ly >= 0) && (ly < Hdim);

    for (int c0 = cbase; c0 < cbase + CIN / NSPLIT; c0 += 8) {
        __syncthreads();
        for (int i = threadIdx.x; i < 18 * 8 * 9; i += 128) {
            int oc = i / 72; int rem = i % 72; int c = rem / 9; int tap = rem % 9;
            ws[c][tap][oc] = w_off[(size_t)oc * CIN * 9 + (size_t)(c0 + c) * 9 + tap];
        }
        {
            float4 v[4];
            if (lyv) {
                const float* xr = xb + (size_t)(c0 + lc) * HW + ly * Wdim + lsg;
#pragma unroll
                for (int j = 0; j < 4; j++) v[j] = *(const float4*)(xr + j * 4);
            } else {
#pragma unroll
                for (int j = 0; j < 4; j++) v[j] = make_float4(0.f, 0.f, 0.f, 0.f);
            }
#pragma unroll
            for (int j = 0; j < 4; j++)
                *(float4*)&xs[lc][lr][lsg + j * 4] = v[j];
        }
        __syncthreads();

#pragma unroll
        for (int c = 0; c < 8; c++) {
            float xv[9];
#pragma unroll
            for (int ky = 0; ky < 3; ky++) {
                const float* row = xs[c][hr + ky];
                xv[ky * 3 + 0] = row[cxm1];
                xv[ky * 3 + 1] = row[cx0];
                xv[ky * 3 + 2] = row[cxp1];
            }
#pragma unroll
            for (int tap = 0; tap < 9; tap++) {
                float xt = xv[tap];
#pragma unroll
                for (int o = 0; o < 18; o++)
                    acc[o] += xt * ws[c][tap][o];
            }
        }
    }

    const int hw = (row2 + hr) * Wdim + wo;
#pragma unroll
    for (int o = 0; o < 18; o++)
        g_offp[split][((size_t)b * 18 + o) * HW + hw] = acc[o];
}

// ---------------------------------------------------------------------------
// Kernel 2: bilinear gather -> g_val[b][c*9+k][hw], tf32-rounded (unchanged)
// ---------------------------------------------------------------------------
__global__ __launch_bounds__(256) void gather_kernel(const float* __restrict__ x)
{
    int idx = blockIdx.x * blockDim.x + threadIdx.x;
    if (idx >= BATCH * KK * HW) return;
    int hw = idx & 4095;
    int k  = (idx >> 12) % KK;
    int b  = idx / (KK * HW);
    int ho = hw >> 6, wo = hw & 63;
    int ky = k / 3,  kx = k % 3;

    const size_t oy = ((size_t)b * 18 + 2 * k + 0) * HW + hw;
    const size_t ox = ((size_t)b * 18 + 2 * k + 1) * HW + hw;
    float dy = 0.f, dx = 0.f;
#pragma unroll
    for (int s = 0; s < NSPLIT; s++) {
        dy += g_offp[s][oy];
        dx += g_offp[s][ox];
    }

    float py = (float)(ho - 1 + ky) + dy;
    float px = (float)(wo - 1 + kx) + dx;
    float y0f = floorf(py), x0f = floorf(px);
    int   y0 = (int)y0f,    x0 = (int)x0f;
    float wy1 = py - y0f, wx1 = px - x0f;
    float wy0 = 1.f - wy1, wx0 = 1.f - wx1;
    int y1 = y0 + 1, x1 = x0 + 1;

    bool vy0 = (y0 >= 0) & (y0 < Hdim);
    bool vy1 = (y1 >= 0) & (y1 < Hdim);
    bool vx0 = (x0 >= 0) & (x0 < Wdim);
    bool vx1 = (x1 >= 0) & (x1 < Wdim);

    float w00 = (vy0 && vx0) ? wy0 * wx0 : 0.f;
    float w01 = (vy0 && vx1) ? wy0 * wx1 : 0.f;
    float w10 = (vy1 && vx0) ? wy1 * wx0 : 0.f;
    float w11 = (vy1 && vx1) ? wy1 * wx1 : 0.f;

    int y0c = min(max(y0, 0), Hdim - 1), y1c = min(max(y1, 0), Hdim - 1);
    int x0c = min(max(x0, 0), Wdim - 1), x1c = min(max(x1, 0), Wdim - 1);
    int i00 = y0c * Wdim + x0c, i01 = y0c * Wdim + x1c;
    int i10 = y1c * Wdim + x0c, i11 = y1c * Wdim + x1c;

    const float* xb = x + (size_t)b * CIN * HW;
    float* vout = g_val + ((size_t)b * PDIM + k) * HW + hw;

    for (int c = 0; c < CIN; c++) {
        const float* xc = xb + c * HW;
        float v = w00 * __ldg(xc + i00) + w01 * __ldg(xc + i01)
                + w10 * __ldg(xc + i10) + w11 * __ldg(xc + i11);
        vout[(size_t)c * KK * HW] = f2tf32(v);
    }
}

// ---------------------------------------------------------------------------
// Kernel 3: TF32 mma.sync GEMM, cp.async-staged.
// Block 128x128, BK=16, 256 thr (8 warps 2x4), warp 64x32.
// As[s][row][20]: permuted k (via g_wdefP); fragment = 1 LDS.128 covering
//   k = {t, t+4, t+8, t+12} (both k8 steps). Conflict-free.
// Bs[s][k][136]: NATURAL k-major rows copied verbatim from g_val via
//   cp.async. Fragment = LDS.32 at [t+4j][n]; stride 136 -> bank 8t+g+c,
//   conflict-free. All staging via cp.async.cg 16B (RF- and L1-bypassed),
//   double-buffered with commit/wait_group.
// ---------------------------------------------------------------------------
#define BM 128
#define BN 128
#define BK 16
#define SA 20    // As row stride (floats)
#define SB 136   // Bs row stride (floats)

__device__ __forceinline__ void mma_tf32(float4& d, float a0, float a1, float a2, float a3,
                                         float b0, float b1) {
    asm volatile(
        "mma.sync.aligned.m16n8k8.row.col.f32.tf32.tf32.f32 "
        "{%0,%1,%2,%3}, {%4,%5,%6,%7}, {%8,%9}, {%0,%1,%2,%3};"
        : "+f"(d.x), "+f"(d.y), "+f"(d.z), "+f"(d.w)
        : "r"(__float_as_uint(a0)), "r"(__float_as_uint(a1)),
          "r"(__float_as_uint(a2)), "r"(__float_as_uint(a3)),
          "r"(__float_as_uint(b0)), "r"(__float_as_uint(b1)));
}

__global__ __launch_bounds__(256, 2) void mma_gemm_kernel(float* __restrict__ C)
{
    __shared__ float As[2][BM][SA];
    __shared__ float Bs[2][BK][SB];

    const int b  = blockIdx.z;
    const float* Bp = g_val + (size_t)b * PDIM * HW;
    float*       Cp = C     + (size_t)b * COUT * HW;
    const int m0 = blockIdx.y * BM;
    const int n0 = blockIdx.x * BN;

    const int tid  = threadIdx.x;
    const int warp = tid >> 5;
    const int lane = tid & 31;
    const int g = lane >> 2;            // 0..7
    const int t = lane & 3;             // 0..3
    const int wm = (warp >> 2) * 64;    // warp M offset
    const int wn = (warp & 3) * 32;     // warp N offset

    float4 acc[4][4];
#pragma unroll
    for (int i = 0; i < 4; i++)
#pragma unroll
        for (int j = 0; j < 4; j++) acc[i][j] = make_float4(0.f, 0.f, 0.f, 0.f);

    // cp.async staging maps
    // A: row = tid>>1, half = tid&1; 2x16B per iter
    const int arow = tid >> 1, ah = tid & 1;
    const float* aP = g_wdefP + (size_t)(m0 + arow) * PDIM + ah * 8;
    const uint32_t asm0 = smem_u32(&As[0][arow][ah * 8]);
    const uint32_t asm1 = smem_u32(&As[1][arow][ah * 8]);
    // B: k = tid>>4, chunk j and j+16; 2x16B per iter
    const int bk = tid >> 4, bj = tid & 15;
    const float* bP = Bp + (size_t)bk * HW + n0 + bj * 4;
    const uint32_t bsm0 = smem_u32(&Bs[0][bk][bj * 4]);
    const uint32_t bsm1 = smem_u32(&Bs[1][bk][bj * 4]);

    const int nk = PDIM / BK;   // 144

    // prologue: stage 0
    cp16(asm0,      aP);
    cp16(asm0 + 16, aP + 4);
    cp16(bsm0,       bP);
    cp16(bsm0 + 256, bP + 64);
    CP_COMMIT();

    for (int it = 0; it < nk; it++) {
        const int s = it & 1;
        const bool more = (it + 1 < nk);

        CP_WAIT0();
        __syncthreads();

        // issue next-stage copies (overlap with compute below)
        if (more) {
            const size_t kt = (size_t)(it + 1) * BK;
            const uint32_t ad = s ? asm0 : asm1;
            const uint32_t bd = s ? bsm0 : bsm1;
            cp16(ad,      aP + kt);
            cp16(ad + 16, aP + kt + 4);
            cp16(bd,       bP + kt * HW);
            cp16(bd + 256, bP + kt * HW + 64);
            CP_COMMIT();
        }

        // B fragments: 4 LDS.32 each, conflict-free (bank = 8t+g+const)
        float4 BB[4];
#pragma unroll
        for (int nt = 0; nt < 4; nt++) {
            const int n = wn + nt * 8 + g;
            BB[nt].x = Bs[s][t     ][n];
            BB[nt].y = Bs[s][t + 4 ][n];
            BB[nt].z = Bs[s][t + 8 ][n];
            BB[nt].w = Bs[s][t + 12][n];
        }

#pragma unroll
        for (int half = 0; half < 2; half++) {
            float4 AL[2], AH[2];
#pragma unroll
            for (int m = 0; m < 2; m++) {
                const int mr = wm + (half * 2 + m) * 16 + g;
                AL[m] = *(const float4*)&As[s][mr][4 * t];
                AH[m] = *(const float4*)&As[s][mr + 8][4 * t];
            }
#pragma unroll
            for (int m = 0; m < 2; m++) {
                const int mt = half * 2 + m;
#pragma unroll
                for (int nt = 0; nt < 4; nt++) {
                    mma_tf32(acc[mt][nt], AL[m].x, AH[m].x, AL[m].y, AH[m].y,
                             BB[nt].x, BB[nt].y);
                    mma_tf32(acc[mt][nt], AL[m].z, AH[m].z, AL[m].w, AH[m].w,
                             BB[nt].z, BB[nt].w);
                }
            }
        }
        __syncthreads();
    }

    // epilogue: D fragments -> gmem
#pragma unroll
    for (int mt = 0; mt < 4; mt++) {
#pragma unroll
        for (int nt = 0; nt < 4; nt++) {
            const int row = m0 + wm + mt * 16 + g;
            const int col = n0 + wn + nt * 8 + 2 * t;
            float4 d = acc[mt][nt];
            *(float2*)(Cp + (size_t)row * HW + col)       = make_float2(d.x, d.y);
            *(float2*)(Cp + (size_t)(row + 8) * HW + col) = make_float2(d.z, d.w);
        }
    }
}

// ---------------------------------------------------------------------------
extern "C" void kernel_launch(void* const* d_in, const int* in_sizes, int n_in,
                              void* d_out, int out_size)
{
    const float* x     = (const float*)d_in[0];   // (4,256,64,64)
    const float* w_def = (const float*)d_in[1];   // (256,256,3,3)
    const float* w_off = (const float*)d_in[2];   // (18,256,3,3)
    float* out = (float*)d_out;                   // (4,256,64,64)

    round_a_kernel<<<(COUT * PDIM + 255) / 256, 256>>>(w_def);
    offsets_part_kernel<<<dim3(BATCH * 32, NSPLIT), 128>>>(x, w_off);
    gather_kernel<<<(BATCH * KK * HW + 255) / 256, 256>>>(x);
    mma_gemm_kernel<<<dim3(HW / BN, COUT / BM, BATCH), 256>>>(out);
}

// round 10
// speedup vs baseline: 1.2292x; 1.0265x over previous
#include <cuda_runtime.h>
#include <cstdint>

// Problem constants
#define Hdim   64
#define Wdim   64
#define HW     4096          // 64*64
#define CIN    256
#define COUT   256
#define BATCH  4
#define KK     9             // 3x3 taps
#define PDIM   (CIN * KK)    // 2304, GEMM K dimension
#define NSPLIT 8             // channel splits for offsets conv

// Scratch (static device globals; no allocation anywhere)
__device__ float g_offp[NSPLIT][BATCH * 18 * HW];        // partial offsets (per channel split)
__device__ float g_val[(size_t)BATCH * PDIM * HW];       // bilinear-sampled matrix (tf32-rounded)
__device__ float g_wdefP[COUT * PDIM];                   // tf32-rounded, k-permuted w_def

__device__ __forceinline__ float f2tf32(float f) {
    unsigned r;
    asm("cvt.rna.tf32.f32 %0, %1;" : "=r"(r) : "f"(f));
    return __uint_as_float(r);
}

__device__ __forceinline__ uint32_t smem_u32(const void* p) {
    uint32_t a;
    asm("{ .reg .u64 t; cvta.to.shared.u64 t, %1; cvt.u32.u64 %0, t; }" : "=r"(a) : "l"(p));
    return a;
}
__device__ __forceinline__ void cp16(uint32_t dst, const void* src) {
    asm volatile("cp.async.cg.shared.global [%0], [%1], 16;" :: "r"(dst), "l"(src));
}
#define CP_COMMIT() asm volatile("cp.async.commit_group;" ::: "memory")
#define CP_WAIT(n)  asm volatile("cp.async.wait_group %0;" :: "n"(n) : "memory")

// ---------------------------------------------------------------------------
// Kernel 0: pre-round w_def to tf32 AND pre-permute k within each 16-group:
// stored float4 group p covers k = {t, t+4, t+8, t+12}. phys p -> orig k:
// k = (p>>2) + 4*(p&1) + 8*((p>>1)&1).
// ---------------------------------------------------------------------------
__global__ __launch_bounds__(256) void round_a_kernel(const float* __restrict__ w)
{
    int i = blockIdx.x * blockDim.x + threadIdx.x;
    if (i >= COUT * PDIM) return;
    int m   = i / PDIM;
    int pos = i % PDIM;
    int kt  = pos & ~15;
    int p   = pos & 15;
    int k   = (p >> 2) + 4 * (p & 1) + 8 * ((p >> 1) & 1);
    g_wdefP[i] = f2tf32(w[(size_t)m * PDIM + kt + k]);
}

// ---------------------------------------------------------------------------
// Kernel 1: partial offsets conv (unchanged; passing since round 6)
// ---------------------------------------------------------------------------
__global__ __launch_bounds__(128) void offsets_part_kernel(
    const float* __restrict__ x, const float* __restrict__ w_off)
{
    __shared__ float ws[8][9][20];
    __shared__ float xs[8][4][68];

    const int blk   = blockIdx.x;
    const int split = blockIdx.y;
    const int b     = blk >> 5;
    const int row2  = (blk & 31) * 2;
    const int hr    = threadIdx.x >> 6;
    const int wo    = threadIdx.x & 63;

    const int cxm1 = (wo == 0)  ? 64 : wo - 1;
    const int cx0  = wo;
    const int cxp1 = (wo == 63) ? 65 : wo + 1;

    if (threadIdx.x < 64) {
        int c = threadIdx.x >> 3;
        int r = (threadIdx.x >> 1) & 3;
        xs[c][r][64 + (threadIdx.x & 1)] = 0.f;
    }

    float acc[18];
#pragma unroll
    for (int o = 0; o < 18; o++) acc[o] = 0.f;

    const float* xb = x + (size_t)b * CIN * HW;
    const int cbase = split * (CIN / NSPLIT);

    const int lc  = threadIdx.x >> 4;
    const int lr  = (threadIdx.x >> 2) & 3;
    const int lsg = (threadIdx.x & 3) * 16;
    const int ly  = row2 - 1 + lr;
    const bool lyv = (ly >= 0) && (ly < Hdim);

    for (int c0 = cbase; c0 < cbase + CIN / NSPLIT; c0 += 8) {
        __syncthreads();
        for (int i = threadIdx.x; i < 18 * 8 * 9; i += 128) {
            int oc = i / 72; int rem = i % 72; int c = rem / 9; int tap = rem % 9;
            ws[c][tap][oc] = w_off[(size_t)oc * CIN * 9 + (size_t)(c0 + c) * 9 + tap];
        }
        {
            float4 v[4];
            if (lyv) {
                const float* xr = xb + (size_t)(c0 + lc) * HW + ly * Wdim + lsg;
#pragma unroll
                for (int j = 0; j < 4; j++) v[j] = *(const float4*)(xr + j * 4);
            } else {
#pragma unroll
                for (int j = 0; j < 4; j++) v[j] = make_float4(0.f, 0.f, 0.f, 0.f);
            }
#pragma unroll
            for (int j = 0; j < 4; j++)
                *(float4*)&xs[lc][lr][lsg + j * 4] = v[j];
        }
        __syncthreads();

#pragma unroll
        for (int c = 0; c < 8; c++) {
            float xv[9];
#pragma unroll
            for (int ky = 0; ky < 3; ky++) {
                const float* row = xs[c][hr + ky];
                xv[ky * 3 + 0] = row[cxm1];
                xv[ky * 3 + 1] = row[cx0];
                xv[ky * 3 + 2] = row[cxp1];
            }
#pragma unroll
            for (int tap = 0; tap < 9; tap++) {
                float xt = xv[tap];
#pragma unroll
                for (int o = 0; o < 18; o++)
                    acc[o] += xt * ws[c][tap][o];
            }
        }
    }

    const int hw = (row2 + hr) * Wdim + wo;
#pragma unroll
    for (int o = 0; o < 18; o++)
        g_offp[split][((size_t)b * 18 + o) * HW + hw] = acc[o];
}

// ---------------------------------------------------------------------------
// Kernel 2: bilinear gather -> g_val[b][c*9+k][hw], tf32-rounded (unchanged)
// ---------------------------------------------------------------------------
__global__ __launch_bounds__(256) void gather_kernel(const float* __restrict__ x)
{
    int idx = blockIdx.x * blockDim.x + threadIdx.x;
    if (idx >= BATCH * KK * HW) return;
    int hw = idx & 4095;
    int k  = (idx >> 12) % KK;
    int b  = idx / (KK * HW);
    int ho = hw >> 6, wo = hw & 63;
    int ky = k / 3,  kx = k % 3;

    const size_t oy = ((size_t)b * 18 + 2 * k + 0) * HW + hw;
    const size_t ox = ((size_t)b * 18 + 2 * k + 1) * HW + hw;
    float dy = 0.f, dx = 0.f;
#pragma unroll
    for (int s = 0; s < NSPLIT; s++) {
        dy += g_offp[s][oy];
        dx += g_offp[s][ox];
    }

    float py = (float)(ho - 1 + ky) + dy;
    float px = (float)(wo - 1 + kx) + dx;
    float y0f = floorf(py), x0f = floorf(px);
    int   y0 = (int)y0f,    x0 = (int)x0f;
    float wy1 = py - y0f, wx1 = px - x0f;
    float wy0 = 1.f - wy1, wx0 = 1.f - wx1;
    int y1 = y0 + 1, x1 = x0 + 1;

    bool vy0 = (y0 >= 0) & (y0 < Hdim);
    bool vy1 = (y1 >= 0) & (y1 < Hdim);
    bool vx0 = (x0 >= 0) & (x0 < Wdim);
    bool vx1 = (x1 >= 0) & (x1 < Wdim);

    float w00 = (vy0 && vx0) ? wy0 * wx0 : 0.f;
    float w01 = (vy0 && vx1) ? wy0 * wx1 : 0.f;
    float w10 = (vy1 && vx0) ? wy1 * wx0 : 0.f;
    float w11 = (vy1 && vx1) ? wy1 * wx1 : 0.f;

    int y0c = min(max(y0, 0), Hdim - 1), y1c = min(max(y1, 0), Hdim - 1);
    int x0c = min(max(x0, 0), Wdim - 1), x1c = min(max(x1, 0), Wdim - 1);
    int i00 = y0c * Wdim + x0c, i01 = y0c * Wdim + x1c;
    int i10 = y1c * Wdim + x0c, i11 = y1c * Wdim + x1c;

    const float* xb = x + (size_t)b * CIN * HW;
    float* vout = g_val + ((size_t)b * PDIM + k) * HW + hw;

    for (int c = 0; c < CIN; c++) {
        const float* xc = xb + c * HW;
        float v = w00 * __ldg(xc + i00) + w01 * __ldg(xc + i01)
                + w10 * __ldg(xc + i10) + w11 * __ldg(xc + i11);
        vout[(size_t)c * KK * HW] = f2tf32(v);
    }
}

// ---------------------------------------------------------------------------
// Kernel 3: TF32 mma.sync GEMM, 4-stage cp.async pipeline.
// Block 128x128, BK=16, 256 thr (8 warps 2x4), warp 64x32.
// As[s][row][20]: permuted k (via g_wdefP); fragment = 1 LDS.128 covering
//   k = {t, t+4, t+8, t+12}. Conflict-free.
// Bs[s][k][136]: natural k-major rows from g_val via cp.async; fragment =
//   LDS.32, conflict-free. STAGES=4, wait_group 2 -> ~2.5 iters of copy
//   slack, hides DRAM-class latency. One __syncthreads per iter.
// Dynamic smem: 4*(10240 + 8704) = 75776 B.
// ---------------------------------------------------------------------------
#define BM 128
#define BN 128
#define BK 16
#define SA 20    // As row stride (floats)
#define SB 136   // Bs row stride (floats)
#define STAGES 4
#define A_STG (BM * SA)            // 2560 floats per A stage
#define B_STG (BK * SB)            // 2176 floats per B stage
#define B_BASE (STAGES * A_STG)    // float offset of B region
#define SMEM_GEMM_BYTES ((STAGES * (A_STG + B_STG)) * 4)   // 75776

__device__ __forceinline__ void mma_tf32(float4& d, float a0, float a1, float a2, float a3,
                                         float b0, float b1) {
    asm volatile(
        "mma.sync.aligned.m16n8k8.row.col.f32.tf32.tf32.f32 "
        "{%0,%1,%2,%3}, {%4,%5,%6,%7}, {%8,%9}, {%0,%1,%2,%3};"
        : "+f"(d.x), "+f"(d.y), "+f"(d.z), "+f"(d.w)
        : "r"(__float_as_uint(a0)), "r"(__float_as_uint(a1)),
          "r"(__float_as_uint(a2)), "r"(__float_as_uint(a3)),
          "r"(__float_as_uint(b0)), "r"(__float_as_uint(b1)));
}

__global__ __launch_bounds__(256, 2) void mma_gemm_kernel(float* __restrict__ C)
{
    extern __shared__ float sm[];

    const int b  = blockIdx.z;
    const float* Bp = g_val + (size_t)b * PDIM * HW;
    float*       Cp = C     + (size_t)b * COUT * HW;
    const int m0 = blockIdx.y * BM;
    const int n0 = blockIdx.x * BN;

    const int tid  = threadIdx.x;
    const int warp = tid >> 5;
    const int lane = tid & 31;
    const int g = lane >> 2;            // 0..7
    const int t = lane & 3;             // 0..3
    const int wm = (warp >> 2) * 64;    // warp M offset
    const int wn = (warp & 3) * 32;     // warp N offset

    float4 acc[4][4];
#pragma unroll
    for (int i = 0; i < 4; i++)
#pragma unroll
        for (int j = 0; j < 4; j++) acc[i][j] = make_float4(0.f, 0.f, 0.f, 0.f);

    // staging maps
    const int arow = tid >> 1, ah = tid & 1;
    const float* aP = g_wdefP + (size_t)(m0 + arow) * PDIM + ah * 8;
    const int bk = tid >> 4, bj = tid & 15;
    const float* bP = Bp + (size_t)bk * HW + n0 + bj * 4;

    const uint32_t smb = smem_u32(sm);
    const uint32_t aoff = (uint32_t)(arow * SA + ah * 8) * 4;
    const uint32_t boff = (uint32_t)(B_BASE + bk * SB + bj * 4) * 4;

    const int nk = PDIM / BK;   // 144

    // prologue: issue STAGES-1 tile copies (one commit group each)
#pragma unroll
    for (int p = 0; p < STAGES - 1; p++) {
        const size_t kt = (size_t)p * BK;
        const uint32_t ad = smb + aoff + p * (A_STG * 4);
        const uint32_t bd = smb + boff + p * (B_STG * 4);
        cp16(ad,      aP + kt);
        cp16(ad + 16, aP + kt + 4);
        cp16(bd,       bP + kt * HW);
        cp16(bd + 256, bP + kt * HW + 64);
        CP_COMMIT();
    }

    for (int it = 0; it < nk; it++) {
        const int s = it & (STAGES - 1);
        const float* Asf = sm + s * A_STG;
        const float* Bsf = sm + B_BASE + s * B_STG;

        CP_WAIT(STAGES - 2);
        __syncthreads();

        // issue copy for tile it+STAGES-1 into stage (s-1)%STAGES
        // (safe: that stage's last readers finished compute(it-1) before the
        //  barrier above)
        if (it + STAGES - 1 < nk) {
            const int d = (s + STAGES - 1) & (STAGES - 1);
            const size_t kt = (size_t)(it + STAGES - 1) * BK;
            const uint32_t ad = smb + aoff + d * (A_STG * 4);
            const uint32_t bd = smb + boff + d * (B_STG * 4);
            cp16(ad,      aP + kt);
            cp16(ad + 16, aP + kt + 4);
            cp16(bd,       bP + kt * HW);
            cp16(bd + 256, bP + kt * HW + 64);
            CP_COMMIT();
        }

        // B fragments: 4 LDS.32 each, conflict-free
        float4 BB[4];
#pragma unroll
        for (int nt = 0; nt < 4; nt++) {
            const int n = wn + nt * 8 + g;
            BB[nt].x = Bsf[(t     ) * SB + n];
            BB[nt].y = Bsf[(t + 4 ) * SB + n];
            BB[nt].z = Bsf[(t + 8 ) * SB + n];
            BB[nt].w = Bsf[(t + 12) * SB + n];
        }

#pragma unroll
        for (int half = 0; half < 2; half++) {
            float4 AL[2], AH[2];
#pragma unroll
            for (int m = 0; m < 2; m++) {
                const int mr = wm + (half * 2 + m) * 16 + g;
                AL[m] = *(const float4*)&Asf[mr * SA + 4 * t];
                AH[m] = *(const float4*)&Asf[(mr + 8) * SA + 4 * t];
            }
#pragma unroll
            for (int m = 0; m < 2; m++) {
                const int mt = half * 2 + m;
#pragma unroll
                for (int nt = 0; nt < 4; nt++) {
                    mma_tf32(acc[mt][nt], AL[m].x, AH[m].x, AL[m].y, AH[m].y,
                             BB[nt].x, BB[nt].y);
                    mma_tf32(acc[mt][nt], AL[m].z, AH[m].z, AL[m].w, AH[m].w,
                             BB[nt].z, BB[nt].w);
                }
            }
        }
    }

    __syncthreads();

    // epilogue: D fragments -> gmem
#pragma unroll
    for (int mt = 0; mt < 4; mt++) {
#pragma unroll
        for (int nt = 0; nt < 4; nt++) {
            const int row = m0 + wm + mt * 16 + g;
            const int col = n0 + wn + nt * 8 + 2 * t;
            float4 d = acc[mt][nt];
            *(float2*)(Cp + (size_t)row * HW + col)       = make_float2(d.x, d.y);
            *(float2*)(Cp + (size_t)(row + 8) * HW + col) = make_float2(d.z, d.w);
        }
    }
}

// ---------------------------------------------------------------------------
extern "C" void kernel_launch(void* const* d_in, const int* in_sizes, int n_in,
                              void* d_out, int out_size)
{
    const float* x     = (const float*)d_in[0];   // (4,256,64,64)
    const float* w_def = (const float*)d_in[1];   // (256,256,3,3)
    const float* w_off = (const float*)d_in[2];   // (18,256,3,3)
    float* out = (float*)d_out;                   // (4,256,64,64)

    cudaFuncSetAttribute(mma_gemm_kernel,
                         cudaFuncAttributeMaxDynamicSharedMemorySize, SMEM_GEMM_BYTES);

    round_a_kernel<<<(COUT * PDIM + 255) / 256, 256>>>(w_def);
    offsets_part_kernel<<<dim3(BATCH * 32, NSPLIT), 128>>>(x, w_off);
    gather_kernel<<<(BATCH * KK * HW + 255) / 256, 256>>>(x);
    mma_gemm_kernel<<<dim3(HW / BN, COUT / BM, BATCH), 256, SMEM_GEMM_BYTES>>>(out);
}

// round 11
// speedup vs baseline: 1.3167x; 1.0712x over previous
#include <cuda_runtime.h>
#include <cstdint>

// Problem constants
#define Hdim   64
#define Wdim   64
#define HW     4096          // 64*64
#define CIN    256
#define COUT   256
#define BATCH  4
#define KK     9             // 3x3 taps
#define PDIM   (CIN * KK)    // 2304, GEMM K dimension
#define NSPLIT 8             // channel splits for offsets conv

// Scratch (static device globals; no allocation anywhere)
__device__ float g_offp[NSPLIT][BATCH * 18 * HW];        // partial offsets (per channel split)
__device__ float g_val[(size_t)BATCH * PDIM * HW];       // bilinear-sampled matrix (tf32-rounded)
__device__ float g_wdefP[COUT * PDIM];                   // tf32-rounded, k-permuted w_def

__device__ __forceinline__ float f2tf32(float f) {
    unsigned r;
    asm("cvt.rna.tf32.f32 %0, %1;" : "=r"(r) : "f"(f));
    return __uint_as_float(r);
}

__device__ __forceinline__ uint32_t smem_u32(const void* p) {
    uint32_t a;
    asm("{ .reg .u64 t; cvta.to.shared.u64 t, %1; cvt.u32.u64 %0, t; }" : "=r"(a) : "l"(p));
    return a;
}
__device__ __forceinline__ void cp16(uint32_t dst, const void* src) {
    asm volatile("cp.async.cg.shared.global [%0], [%1], 16;" :: "r"(dst), "l"(src));
}
#define CP_COMMIT() asm volatile("cp.async.commit_group;" ::: "memory")
#define CP_WAIT(n)  asm volatile("cp.async.wait_group %0;" :: "n"(n) : "memory")

// ---------------------------------------------------------------------------
// Kernel 0: pre-round w_def to tf32 AND pre-permute k within each 16-group:
// stored float4 group p covers k = {t, t+4, t+8, t+12}. phys p -> orig k:
// k = (p>>2) + 4*(p&1) + 8*((p>>1)&1).
// ---------------------------------------------------------------------------
__global__ __launch_bounds__(256) void round_a_kernel(const float* __restrict__ w)
{
    int i = blockIdx.x * blockDim.x + threadIdx.x;
    if (i >= COUT * PDIM) return;
    int m   = i / PDIM;
    int pos = i % PDIM;
    int kt  = pos & ~15;
    int p   = pos & 15;
    int k   = (p >> 2) + 4 * (p & 1) + 8 * ((p >> 1) & 1);
    g_wdefP[i] = f2tf32(w[(size_t)m * PDIM + kt + k]);
}

// ---------------------------------------------------------------------------
// Kernel 1: partial offsets conv (unchanged; passing since round 6)
// ---------------------------------------------------------------------------
__global__ __launch_bounds__(128) void offsets_part_kernel(
    const float* __restrict__ x, const float* __restrict__ w_off)
{
    __shared__ float ws[8][9][20];
    __shared__ float xs[8][4][68];

    const int blk   = blockIdx.x;
    const int split = blockIdx.y;
    const int b     = blk >> 5;
    const int row2  = (blk & 31) * 2;
    const int hr    = threadIdx.x >> 6;
    const int wo    = threadIdx.x & 63;

    const int cxm1 = (wo == 0)  ? 64 : wo - 1;
    const int cx0  = wo;
    const int cxp1 = (wo == 63) ? 65 : wo + 1;

    if (threadIdx.x < 64) {
        int c = threadIdx.x >> 3;
        int r = (threadIdx.x >> 1) & 3;
        xs[c][r][64 + (threadIdx.x & 1)] = 0.f;
    }

    float acc[18];
#pragma unroll
    for (int o = 0; o < 18; o++) acc[o] = 0.f;

    const float* xb = x + (size_t)b * CIN * HW;
    const int cbase = split * (CIN / NSPLIT);

    const int lc  = threadIdx.x >> 4;
    const int lr  = (threadIdx.x >> 2) & 3;
    const int lsg = (threadIdx.x & 3) * 16;
    const int ly  = row2 - 1 + lr;
    const bool lyv = (ly >= 0) && (ly < Hdim);

    for (int c0 = cbase; c0 < cbase + CIN / NSPLIT; c0 += 8) {
        __syncthreads();
        for (int i = threadIdx.x; i < 18 * 8 * 9; i += 128) {
            int oc = i / 72; int rem = i % 72; int c = rem / 9; int tap = rem % 9;
            ws[c][tap][oc] = w_off[(size_t)oc * CIN * 9 + (size_t)(c0 + c) * 9 + tap];
        }
        {
            float4 v[4];
            if (lyv) {
                const float* xr = xb + (size_t)(c0 + lc) * HW + ly * Wdim + lsg;
#pragma unroll
                for (int j = 0; j < 4; j++) v[j] = *(const float4*)(xr + j * 4);
            } else {
#pragma unroll
                for (int j = 0; j < 4; j++) v[j] = make_float4(0.f, 0.f, 0.f, 0.f);
            }
#pragma unroll
            for (int j = 0; j < 4; j++)
                *(float4*)&xs[lc][lr][lsg + j * 4] = v[j];
        }
        __syncthreads();

#pragma unroll
        for (int c = 0; c < 8; c++) {
            float xv[9];
#pragma unroll
            for (int ky = 0; ky < 3; ky++) {
                const float* row = xs[c][hr + ky];
                xv[ky * 3 + 0] = row[cxm1];
                xv[ky * 3 + 1] = row[cx0];
                xv[ky * 3 + 2] = row[cxp1];
            }
#pragma unroll
            for (int tap = 0; tap < 9; tap++) {
                float xt = xv[tap];
#pragma unroll
                for (int o = 0; o < 18; o++)
                    acc[o] += xt * ws[c][tap][o];
            }
        }
    }

    const int hw = (row2 + hr) * Wdim + wo;
#pragma unroll
    for (int o = 0; o < 18; o++)
        g_offp[split][((size_t)b * 18 + o) * HW + hw] = acc[o];
}

// ---------------------------------------------------------------------------
// Kernel 2: bilinear gather -> g_val[b][c*9+k][hw], tf32-rounded (unchanged)
// ---------------------------------------------------------------------------
__global__ __launch_bounds__(256) void gather_kernel(const float* __restrict__ x)
{
    int idx = blockIdx.x * blockDim.x + threadIdx.x;
    if (idx >= BATCH * KK * HW) return;
    int hw = idx & 4095;
    int k  = (idx >> 12) % KK;
    int b  = idx / (KK * HW);
    int ho = hw >> 6, wo = hw & 63;
    int ky = k / 3,  kx = k % 3;

    const size_t oy = ((size_t)b * 18 + 2 * k + 0) * HW + hw;
    const size_t ox = ((size_t)b * 18 + 2 * k + 1) * HW + hw;
    float dy = 0.f, dx = 0.f;
#pragma unroll
    for (int s = 0; s < NSPLIT; s++) {
        dy += g_offp[s][oy];
        dx += g_offp[s][ox];
    }

    float py = (float)(ho - 1 + ky) + dy;
    float px = (float)(wo - 1 + kx) + dx;
    float y0f = floorf(py), x0f = floorf(px);
    int   y0 = (int)y0f,    x0 = (int)x0f;
    float wy1 = py - y0f, wx1 = px - x0f;
    float wy0 = 1.f - wy1, wx0 = 1.f - wx1;
    int y1 = y0 + 1, x1 = x0 + 1;

    bool vy0 = (y0 >= 0) & (y0 < Hdim);
    bool vy1 = (y1 >= 0) & (y1 < Hdim);
    bool vx0 = (x0 >= 0) & (x0 < Wdim);
    bool vx1 = (x1 >= 0) & (x1 < Wdim);

    float w00 = (vy0 && vx0) ? wy0 * wx0 : 0.f;
    float w01 = (vy0 && vx1) ? wy0 * wx1 : 0.f;
    float w10 = (vy1 && vx0) ? wy1 * wx0 : 0.f;
    float w11 = (vy1 && vx1) ? wy1 * wx1 : 0.f;

    int y0c = min(max(y0, 0), Hdim - 1), y1c = min(max(y1, 0), Hdim - 1);
    int x0c = min(max(x0, 0), Wdim - 1), x1c = min(max(x1, 0), Wdim - 1);
    int i00 = y0c * Wdim + x0c, i01 = y0c * Wdim + x1c;
    int i10 = y1c * Wdim + x0c, i11 = y1c * Wdim + x1c;

    const float* xb = x + (size_t)b * CIN * HW;
    float* vout = g_val + ((size_t)b * PDIM + k) * HW + hw;

    for (int c = 0; c < CIN; c++) {
        const float* xc = xb + c * HW;
        float v = w00 * __ldg(xc + i00) + w01 * __ldg(xc + i01)
                + w10 * __ldg(xc + i10) + w11 * __ldg(xc + i11);
        vout[(size_t)c * KK * HW] = f2tf32(v);
    }
}

// ---------------------------------------------------------------------------
// Kernel 3: TF32 mma.sync GEMM, 4-stage cp.async pipeline.
// Block 128x128, BK=16, 256 thr (8 warps 2x4), warp 64x32.
// As[s][row][16] (SA=16, NO padding): fragment LDS.128 at [row][4t] hits
//   bank16 = (4*row + t) mod 8; a phase (rows g,g+1 x t0..3) covers
//   {4g+t} u {4g+4+t} = 8 distinct banks -> conflict-free. (SA=20 had a
//   2-way phase conflict: 5g+8 == 5g mod 8.)
// Bs[s][k][136]: natural k-major rows via cp.async; LDS.32 fragments,
//   bank32 = 8t+g+const, conflict-free. STAGES=4, wait_group 2.
// Dynamic smem: 4*(8192 + 8704) = 67584 B.
// ---------------------------------------------------------------------------
#define BM 128
#define BN 128
#define BK 16
#define SA 16    // As row stride (floats) — conflict-free for 4t-based LDS.128
#define SB 136   // Bs row stride (floats)
#define STAGES 4
#define A_STG (BM * SA)            // 2048 floats per A stage
#define B_STG (BK * SB)            // 2176 floats per B stage
#define B_BASE (STAGES * A_STG)    // float offset of B region
#define SMEM_GEMM_BYTES ((STAGES * (A_STG + B_STG)) * 4)   // 67584

__device__ __forceinline__ void mma_tf32(float4& d, float a0, float a1, float a2, float a3,
                                         float b0, float b1) {
    asm volatile(
        "mma.sync.aligned.m16n8k8.row.col.f32.tf32.tf32.f32 "
        "{%0,%1,%2,%3}, {%4,%5,%6,%7}, {%8,%9}, {%0,%1,%2,%3};"
        : "+f"(d.x), "+f"(d.y), "+f"(d.z), "+f"(d.w)
        : "r"(__float_as_uint(a0)), "r"(__float_as_uint(a1)),
          "r"(__float_as_uint(a2)), "r"(__float_as_uint(a3)),
          "r"(__float_as_uint(b0)), "r"(__float_as_uint(b1)));
}

__global__ __launch_bounds__(256, 2) void mma_gemm_kernel(float* __restrict__ C)
{
    extern __shared__ float sm[];

    const int b  = blockIdx.z;
    const float* Bp = g_val + (size_t)b * PDIM * HW;
    float*       Cp = C     + (size_t)b * COUT * HW;
    const int m0 = blockIdx.y * BM;
    const int n0 = blockIdx.x * BN;

    const int tid  = threadIdx.x;
    const int warp = tid >> 5;
    const int lane = tid & 31;
    const int g = lane >> 2;            // 0..7
    const int t = lane & 3;             // 0..3
    const int wm = (warp >> 2) * 64;    // warp M offset
    const int wn = (warp & 3) * 32;     // warp N offset

    float4 acc[4][4];
#pragma unroll
    for (int i = 0; i < 4; i++)
#pragma unroll
        for (int j = 0; j < 4; j++) acc[i][j] = make_float4(0.f, 0.f, 0.f, 0.f);

    // staging maps
    const int arow = tid >> 1, ah = tid & 1;
    const float* aP = g_wdefP + (size_t)(m0 + arow) * PDIM + ah * 8;
    const int bk = tid >> 4, bj = tid & 15;
    const float* bP = Bp + (size_t)bk * HW + n0 + bj * 4;

    const uint32_t smb = smem_u32(sm);
    const uint32_t aoff = (uint32_t)(arow * SA + ah * 8) * 4;
    const uint32_t boff = (uint32_t)(B_BASE + bk * SB + bj * 4) * 4;

    const int nk = PDIM / BK;   // 144

    // prologue: issue STAGES-1 tile copies (one commit group each)
#pragma unroll
    for (int p = 0; p < STAGES - 1; p++) {
        const size_t kt = (size_t)p * BK;
        const uint32_t ad = smb + aoff + p * (A_STG * 4);
        const uint32_t bd = smb + boff + p * (B_STG * 4);
        cp16(ad,      aP + kt);
        cp16(ad + 16, aP + kt + 4);
        cp16(bd,       bP + kt * HW);
        cp16(bd + 256, bP + kt * HW + 64);
        CP_COMMIT();
    }

    for (int it = 0; it < nk; it++) {
        const int s = it & (STAGES - 1);
        const float* Asf = sm + s * A_STG;
        const float* Bsf = sm + B_BASE + s * B_STG;

        CP_WAIT(STAGES - 2);
        __syncthreads();

        // issue copy for tile it+STAGES-1 into stage (s-1)%STAGES
        if (it + STAGES - 1 < nk) {
            const int d = (s + STAGES - 1) & (STAGES - 1);
            const size_t kt = (size_t)(it + STAGES - 1) * BK;
            const uint32_t ad = smb + aoff + d * (A_STG * 4);
            const uint32_t bd = smb + boff + d * (B_STG * 4);
            cp16(ad,      aP + kt);
            cp16(ad + 16, aP + kt + 4);
            cp16(bd,       bP + kt * HW);
            cp16(bd + 256, bP + kt * HW + 64);
            CP_COMMIT();
        }

        // B fragments: 4 LDS.32 each, conflict-free
        float4 BB[4];
#pragma unroll
        for (int nt = 0; nt < 4; nt++) {
            const int n = wn + nt * 8 + g;
            BB[nt].x = Bsf[(t     ) * SB + n];
            BB[nt].y = Bsf[(t + 4 ) * SB + n];
            BB[nt].z = Bsf[(t + 8 ) * SB + n];
            BB[nt].w = Bsf[(t + 12) * SB + n];
        }

#pragma unroll
        for (int half = 0; half < 2; half++) {
            float4 AL[2], AH[2];
#pragma unroll
            for (int m = 0; m < 2; m++) {
                const int mr = wm + (half * 2 + m) * 16 + g;
                AL[m] = *(const float4*)&Asf[mr * SA + 4 * t];
                AH[m] = *(const float4*)&Asf[(mr + 8) * SA + 4 * t];
            }
#pragma unroll
            for (int m = 0; m < 2; m++) {
                const int mt = half * 2 + m;
#pragma unroll
                for (int nt = 0; nt < 4; nt++) {
                    mma_tf32(acc[mt][nt], AL[m].x, AH[m].x, AL[m].y, AH[m].y,
                             BB[nt].x, BB[nt].y);
                    mma_tf32(acc[mt][nt], AL[m].z, AH[m].z, AL[m].w, AH[m].w,
                             BB[nt].z, BB[nt].w);
                }
            }
        }
    }

    __syncthreads();

    // epilogue: D fragments -> gmem
#pragma unroll
    for (int mt = 0; mt < 4; mt++) {
#pragma unroll
        for (int nt = 0; nt < 4; nt++) {
            const int row = m0 + wm + mt * 16 + g;
            const int col = n0 + wn + nt * 8 + 2 * t;
            float4 d = acc[mt][nt];
            *(float2*)(Cp + (size_t)row * HW + col)       = make_float2(d.x, d.y);
            *(float2*)(Cp + (size_t)(row + 8) * HW + col) = make_float2(d.z, d.w);
        }
    }
}

// ---------------------------------------------------------------------------
extern "C" void kernel_launch(void* const* d_in, const int* in_sizes, int n_in,
                              void* d_out, int out_size)
{
    const float* x     = (const float*)d_in[0];   // (4,256,64,64)
    const float* w_def = (const float*)d_in[1];   // (256,256,3,3)
    const float* w_off = (const float*)d_in[2];   // (18,256,3,3)
    float* out = (float*)d_out;                   // (4,256,64,64)

    cudaFuncSetAttribute(mma_gemm_kernel,
                         cudaFuncAttributeMaxDynamicSharedMemorySize, SMEM_GEMM_BYTES);

    round_a_kernel<<<(COUT * PDIM + 255) / 256, 256>>>(w_def);
    offsets_part_kernel<<<dim3(BATCH * 32, NSPLIT), 128>>>(x, w_off);
    gather_kernel<<<(BATCH * KK * HW + 255) / 256, 256>>>(x);
    mma_gemm_kernel<<<dim3(HW / BN, COUT / BM, BATCH), 256, SMEM_GEMM_BYTES>>>(out);
}